// round 7
// baseline (speedup 1.0000x reference)
#include <cuda_runtime.h>
#include <cstdint>

#define NB    32
#define NT    24
#define SZ    768
#define NS    6
#define SLAB  128
#define NTHR  512
#define NWARP 16
#define RPF4  (SZ / 4)      // 192 float4 per matrix row

// post-ReLU carry produced at step t, consumed at step t+1
__device__ float g_carry[NT][NB][SZ];
// per-slab flags: g_flag[t][b][s] = 1 when slab s of (t,b) carry is visible
__device__ int g_flag[NT][NB][NS];

__global__ void init_flags_kernel() {
    int i = blockIdx.x * blockDim.x + threadIdx.x;
    if (i < NT * NB * NS) ((int*)g_flag)[i] = 0;
}

#define FMA_ROW(cyv, mr)                     \
    acc.x = fmaf((cyv), (mr).x, acc.x);      \
    acc.y = fmaf((cyv), (mr).y, acc.y);      \
    acc.z = fmaf((cyv), (mr).z, acc.z);      \
    acc.w = fmaf((cyv), (mr).w, acc.w);

__global__ void __launch_bounds__(NTHR, 2)   // cap regs at 64: 2 blocks/SM co-residency
scan_kernel(const float* __restrict__ inp,
            const float* __restrict__ param,
            float* __restrict__ out)
{
    __shared__ float4 s_red[NWARP][32];      // 8 KB partials

    const int s    = blockIdx.x;             // slab 0..5 (owns columns kbase..kbase+127)
    const int b    = blockIdx.y;             // batch
    const int tid  = threadIdx.x;
    const int w    = tid >> 5;
    const int lane = tid & 31;
    const int kbase = s * SLAB;

    // float4 view of this batch's matrices, offset to our column slab.
    // pm[row*RPF4 + lane] = columns kbase + 4*lane .. +3 of that row.
    const float4* matb = (const float4*)(inp + (size_t)b * NT * SZ * SZ + kbase);

    // Preload subchunk 0 (chunk 0, rows w*8..w*8+3) of t=0.
    float4 m0, m1, m2, m3;
    {
        const int r0 = w * 8;
        m0 = __ldcs(&matb[(size_t)(r0 + 0) * RPF4 + lane]);
        m1 = __ldcs(&matb[(size_t)(r0 + 1) * RPF4 + lane]);
        m2 = __ldcs(&matb[(size_t)(r0 + 2) * RPF4 + lane]);
        m3 = __ldcs(&matb[(size_t)(r0 + 3) * RPF4 + lane]);
    }

    for (int t = 0; t < NT; ++t) {
        const float4* pm = matb + (size_t)t * SZ * RPF4;
        float4 acc = make_float4(0.f, 0.f, 0.f, 0.f);

        // 12 subchunks of 4 rows each; chunk c = sc>>1 needs only slab-c carry.
        #pragma unroll
        for (int sc = 0; sc < 12; ++sc) {
            const int c    = sc >> 1;
            const int h    = sc & 1;
            const int rowb = c * SLAB + w * 8 + 4 * h;   // first of this sub's 4 rows

            // ---- issue NEXT subchunk's matrix loads before any waiting ----
            float4 n0 = m0, n1 = m1, n2 = m2, n3 = m3;
            if (sc < 11) {
                const int nr = ((sc + 1) >> 1) * SLAB + w * 8 + 4 * ((sc + 1) & 1);
                n0 = __ldcs(&pm[(size_t)(nr + 0) * RPF4 + lane]);
                n1 = __ldcs(&pm[(size_t)(nr + 1) * RPF4 + lane]);
                n2 = __ldcs(&pm[(size_t)(nr + 2) * RPF4 + lane]);
                n3 = __ldcs(&pm[(size_t)(nr + 3) * RPF4 + lane]);
            } else if (t < NT - 1) {
                // step-boundary prefetch: subchunk 0 of step t+1
                const float4* pn = pm + (size_t)SZ * RPF4;
                const int nr = w * 8;
                n0 = __ldcs(&pn[(size_t)(nr + 0) * RPF4 + lane]);
                n1 = __ldcs(&pn[(size_t)(nr + 1) * RPF4 + lane]);
                n2 = __ldcs(&pn[(size_t)(nr + 2) * RPF4 + lane]);
                n3 = __ldcs(&pn[(size_t)(nr + 3) * RPF4 + lane]);
            }

            // ---- per-warp wait on just THIS source chunk's producer ----
            if (h == 0 && t > 0) {
                volatile int* f = &g_flag[t - 1][b][c];
                while (*f == 0) __nanosleep(20);
                __threadfence();                          // acquire
            }

            // ---- carry values for these 4 rows (broadcast float4) ----
            float4 cy;
            if (t == 0) {
                cy = ((const float4*)param)[rowb >> 2];
                cy.x += 1.f; cy.y += 1.f; cy.z += 1.f; cy.w += 1.f;
            } else {
                cy = __ldcg((const float4*)&g_carry[t - 1][b][rowb]);
            }

            FMA_ROW(cy.x, m0);
            FMA_ROW(cy.y, m1);
            FMA_ROW(cy.z, m2);
            FMA_ROW(cy.w, m3);

            m0 = n0; m1 = n1; m2 = n2; m3 = n3;
        }

        // ---- cross-warp reduction (only block-wide sync points) ----
        s_red[w][lane] = acc;
        __syncthreads();

        if (tid < SLAB) {
            // flat slab col r: lane = r>>2, component = r&3
            float sum = 0.f;
            #pragma unroll
            for (int ww = 0; ww < NWARP; ++ww)
                sum += ((const float*)&s_red[ww][tid >> 2])[tid & 3];
            const int k = kbase + tid;
            if (t == NT - 1) {
                out[b * SZ + k] = sum;                    // pre-ReLU final step
            } else {
                __stcg(&g_carry[t][b][k], fmaxf(sum, 0.f));
            }
            __threadfence();                              // release (writers only)
        }
        __syncthreads();                                  // writers fenced before flag
        if (t < NT - 1 && tid == 0) {
            atomicExch(&g_flag[t][b][s], 1);
        }
    }
}

extern "C" void kernel_launch(void* const* d_in, const int* in_sizes, int n_in,
                              void* d_out, int out_size)
{
    const float* inp   = (const float*)d_in[0];   // [32,24,768,768] f32
    const float* param = (const float*)d_in[1];   // [768] f32
    float* out         = (float*)d_out;           // [32,768] f32

    init_flags_kernel<<<9, 512>>>();
    dim3 grid(NS, NB);
    scan_kernel<<<grid, NTHR>>>(inp, param, out);
}